// round 9
// baseline (speedup 1.0000x reference)
#include <cuda_runtime.h>
#include <cuda_fp16.h>

#define NODELEN 10
#define DEG 32
#define MAXN 200000
#define PADH 16   // halves per row: 32B = one sector, sector-aligned

// Allocation-free scratch: fp16 gather tables, one sector per row.
__device__ __half g_featH[(size_t)MAXN * PADH];
__device__ __half g_h1H[(size_t)MAXN * PADH];

// ---------------------------------------------------------------------------
// Pack: features [N,10] fp32 -> g_featH [N,16] fp16 (zero padded).
// ---------------------------------------------------------------------------
__global__ __launch_bounds__(256) void pack_features_kernel(
    const float* __restrict__ features, int N)
{
    int idx = blockIdx.x * blockDim.x + threadIdx.x;
    if (idx >= N * PADH) return;
    int n = idx >> 4;
    int k = idx & 15;
    float v = (k < NODELEN) ? features[(size_t)n * NODELEN + k] : 0.f;
    g_featH[idx] = __float2half_rn(v);
}

// ---------------------------------------------------------------------------
// Hop 1: one warp per TWO nodes. Each gathered row = 16 halves = 32B = one
// sector -> 1 L1tex wavefront per random row.
// ---------------------------------------------------------------------------
__global__ __launch_bounds__(256) void hop1_kernel(
    const int* __restrict__ adj, int N)
{
    int w    = (blockIdx.x * blockDim.x + threadIdx.x) >> 5;
    int lane = threadIdx.x & 31;
    int n0 = 2 * w, n1 = 2 * w + 1;
    if (n0 >= N) return;
    bool has1 = (n1 < N);

    int nb0 = adj[(size_t)n0 * DEG + lane];
    int nb1 = has1 ? adj[(size_t)n1 * DEG + lane] : nb0;

    int r = lane >> 3, j = lane & 7;
    float2 a0 = make_float2(0.f, 0.f), a1 = make_float2(0.f, 0.f);
#pragma unroll
    for (int i = 0; i < 8; i++) {
        int m0 = __shfl_sync(0xffffffffu, nb0, 4 * i + r);
        int m1 = __shfl_sync(0xffffffffu, nb1, 4 * i + r);
        float2 v0 = __half22float2(*reinterpret_cast<const __half2*>(
            g_featH + (size_t)m0 * PADH + 2 * j));
        float2 v1 = __half22float2(*reinterpret_cast<const __half2*>(
            g_featH + (size_t)m1 * PADH + 2 * j));
        a0.x += v0.x; a0.y += v0.y;
        a1.x += v1.x; a1.y += v1.y;
    }
#pragma unroll
    for (int off = 8; off < 32; off <<= 1) {
        a0.x += __shfl_xor_sync(0xffffffffu, a0.x, off);
        a0.y += __shfl_xor_sync(0xffffffffu, a0.y, off);
        a1.x += __shfl_xor_sync(0xffffffffu, a1.x, off);
        a1.y += __shfl_xor_sync(0xffffffffu, a1.y, off);
    }

    if (lane < 16) {
        int   node = (lane >> 3) ? n1 : n0;
        float2 s   = (lane >> 3) ? a1 : a0;
        if (node < N) {
            float vx = s.x * (1.f / 32.f);
            float vy = s.y * (1.f / 32.f);
            if (j == 0) vx = 0.f;            // h1[:,0] = 0
            *reinterpret_cast<__half2*>(g_h1H + (size_t)node * PADH + 2 * j) =
                __floats2half2_rn(vx, vy);
        }
    }
}

// ---------------------------------------------------------------------------
// f32x2 helpers (sm_103a packed FFMA2)
// ---------------------------------------------------------------------------
typedef unsigned long long u64;

__device__ __forceinline__ u64 pk2(float lo, float hi) {
    u64 r; asm("mov.b64 %0,{%1,%2};" : "=l"(r) : "f"(lo), "f"(hi)); return r;
}
__device__ __forceinline__ void up2(u64 v, float& lo, float& hi) {
    asm("mov.b64 {%0,%1},%2;" : "=f"(lo), "=f"(hi) : "l"(v));
}
__device__ __forceinline__ u64 fma2(u64 a, u64 b, u64 c) {
    u64 d; asm("fma.rn.f32x2 %0,%1,%2,%3;" : "=l"(d) : "l"(a), "l"(b), "l"(c));
    return d;
}

// One dense layer: out[2p],out[2p+1] = (relu?) ( sum_j W[2p..2p+1][j]*in[j]+b )
template<int I, int P, bool RELU>
__device__ __forceinline__ void layer2(const u64* __restrict__ w,
                                       const u64* __restrict__ b,
                                       const float* __restrict__ in,
                                       float* __restrict__ out)
{
    u64 acc[P];
#pragma unroll
    for (int p = 0; p < P; p++) acc[p] = b[p];
#pragma unroll
    for (int j = 0; j < I; j++) {
        float xv = in[j];
        u64 xj = pk2(xv, xv);
#pragma unroll
        for (int p = 0; p < P; p++)
            acc[p] = fma2(w[j * P + p], xj, acc[p]);
    }
#pragma unroll
    for (int p = 0; p < P; p++) {
        float lo, hi; up2(acc[p], lo, hi);
        if (RELU) { lo = fmaxf(lo, 0.f); hi = fmaxf(hi, 0.f); }
        out[2 * p]     = lo;
        out[2 * p + 1] = hi;
    }
}

// smem u64 offsets for the 6 layers (W then biases)
#define OFF_W1 0      // 20*8  = 160
#define OFF_W2 160    // 15*5  = 75
#define OFF_W3 235    // 10*3  = 30
#define OFF_W4 265    // 5*5   = 25
#define OFF_W5 290    // 10*8  = 80
#define OFF_W6 370    // 15*10 = 150
#define OFF_B1 520
#define OFF_B2 528
#define OFF_B3 533
#define OFF_B4 536
#define OFF_B5 541
#define OFF_B6 549
#define SW_U64 560

#define BLK 256
#define EMB_PAD 21   // odd stride -> conflict-free LDS

// ---------------------------------------------------------------------------
// FUSED hop2 + emb + MLP. Block = 256 threads = 256 nodes.
// Phase A: 8 warps gather agg (from g_h1H) + self features for 32 nodes each
//          into the smem tile se[256][21].
// Phase B: export emb tile (coalesced), then each thread runs the MLP for one
//          node; decoded overwrites its own se row; export decoded tile.
// ---------------------------------------------------------------------------
__global__ __launch_bounds__(BLK) void hop2_mlp_kernel(
    const float* __restrict__ features, const int* __restrict__ adj,
    const float* __restrict__ We1, const float* __restrict__ be1,
    const float* __restrict__ We2, const float* __restrict__ be2,
    const float* __restrict__ We3, const float* __restrict__ be3,
    const float* __restrict__ Wd1, const float* __restrict__ bd1,
    const float* __restrict__ Wd2, const float* __restrict__ bd2,
    const float* __restrict__ Wd3, const float* __restrict__ bd3,
    float* __restrict__ emb_out, float* __restrict__ enc_out,
    float* __restrict__ dec_out, int N)
{
    __shared__ __align__(16) u64 sw[SW_U64];
    __shared__ float se[BLK * EMB_PAD];

    const int tid  = threadIdx.x;
    const int wid  = tid >> 5;
    const int lane = tid & 31;
    const int base = blockIdx.x * BLK;

    // ---- weight prep (runs concurrently with gather in other warps' view;
    //      all warps do a slice, barrier below covers both) ----
    {
        const float* Ws[6] = {We1, We2, We3, Wd1, Wd2, Wd3};
        const float* Bs[6] = {be1, be2, be3, bd1, bd2, bd3};
        const int Is[6] = {20, 15, 10, 5, 10, 15};
        const int Os[6] = {15, 10, 5, 10, 15, 20};
        const int Ps[6] = {8, 5, 3, 5, 8, 10};
        const int oW[6] = {OFF_W1, OFF_W2, OFF_W3, OFF_W4, OFF_W5, OFF_W6};
        const int oB[6] = {OFF_B1, OFF_B2, OFF_B3, OFF_B4, OFF_B5, OFF_B6};
        for (int l = 0; l < 6; l++) {
            int I = Is[l], O = Os[l], P = Ps[l];
            const float* W = Ws[l];
            for (int idx = tid; idx < I * P; idx += BLK) {
                int j = idx / P, p = idx % P;
                int r0 = 2 * p, r1 = 2 * p + 1;
                float w0 = (r0 < O) ? W[r0 * I + j] : 0.f;
                float w1 = (r1 < O) ? W[r1 * I + j] : 0.f;
                reinterpret_cast<float2*>(sw)[oW[l] + idx] = make_float2(w0, w1);
            }
            const float* B = Bs[l];
            for (int p = tid; p < P; p += BLK) {
                int r0 = 2 * p, r1 = 2 * p + 1;
                float b0 = (r0 < O) ? B[r0] : 0.f;
                float b1 = (r1 < O) ? B[r1] : 0.f;
                reinterpret_cast<float2*>(sw)[oB[l] + p] = make_float2(b0, b1);
            }
        }
    }

    // ---- Phase A: gather. Warp wid handles local nodes [wid*32, wid*32+32),
    //      two nodes per iteration (16 gather LDGs in flight). ----
    const int r = lane >> 3, j = lane & 7;
#pragma unroll 2
    for (int it = 0; it < 16; it++) {
        int ln0 = (wid << 5) + 2 * it;
        int ln1 = ln0 + 1;
        int n0 = base + ln0, n1 = base + ln1;
        bool v0b = (n0 < N), v1b = (n1 < N);

        int nb0 = v0b ? adj[(size_t)n0 * DEG + lane] : 0;
        int nb1 = v1b ? adj[(size_t)n1 * DEG + lane] : 0;

        float2 a0 = make_float2(0.f, 0.f), a1 = make_float2(0.f, 0.f);
#pragma unroll
        for (int i = 0; i < 8; i++) {
            int m0 = __shfl_sync(0xffffffffu, nb0, 4 * i + r);
            int m1 = __shfl_sync(0xffffffffu, nb1, 4 * i + r);
            float2 q0 = __half22float2(*reinterpret_cast<const __half2*>(
                g_h1H + (size_t)m0 * PADH + 2 * j));
            float2 q1 = __half22float2(*reinterpret_cast<const __half2*>(
                g_h1H + (size_t)m1 * PADH + 2 * j));
            a0.x += q0.x; a0.y += q0.y;
            a1.x += q1.x; a1.y += q1.y;
        }
#pragma unroll
        for (int off = 8; off < 32; off <<= 1) {
            a0.x += __shfl_xor_sync(0xffffffffu, a0.x, off);
            a0.y += __shfl_xor_sync(0xffffffffu, a0.y, off);
            a1.x += __shfl_xor_sync(0xffffffffu, a1.x, off);
            a1.y += __shfl_xor_sync(0xffffffffu, a1.y, off);
        }

        // agg -> se cols 10..19 (pairs j=0..4), col 10 zeroed
        if (lane < 16 && j < 5) {
            int  ln   = (lane >> 3) ? ln1 : ln0;
            bool valid= (lane >> 3) ? v1b : v0b;
            float2 s  = (lane >> 3) ? a1 : a0;
            if (valid) {
                float vx = s.x * (1.f / 32.f);
                float vy = s.y * (1.f / 32.f);
                if (j == 0) vx = 0.f;        // emb[:,NODELEN] = 0
                se[ln * EMB_PAD + 10 + 2 * j]     = vx;
                se[ln * EMB_PAD + 10 + 2 * j + 1] = vy;
            }
        }
        // self features -> se cols 0..9, col 0 zeroed
        if (lane >= 12) {
            int d, ln, node; bool valid;
            if (lane < 22) { d = lane - 12; ln = ln0; node = n0; valid = v0b; }
            else           { d = lane - 22; ln = ln1; node = n1; valid = v1b; }
            if (valid) {
                float f = (d == 0) ? 0.f : features[(size_t)node * NODELEN + d];
                se[ln * EMB_PAD + d] = f;
            }
        }
    }
    __syncthreads();

    // ---- export emb tile (coalesced float4) ----
    const long f4base  = (long)base * 5;
    const long f4total = (long)N * 5;
#pragma unroll
    for (int i = 0; i < 5; i++) {
        int  lf4 = tid + i * BLK;
        long f4  = f4base + lf4;
        if (f4 < f4total) {
            int rr = lf4 / 5, q = lf4 % 5;
            const float* s = se + rr * EMB_PAD + q * 4;
            reinterpret_cast<float4*>(emb_out)[f4] =
                make_float4(s[0], s[1], s[2], s[3]);
        }
    }
    __syncthreads();   // emb export must finish before decode overwrites se

    // ---- Phase B: MLP, one node per thread ----
    const int n = base + tid;
    float* myrow = se + tid * EMB_PAD;

    float h1v[16], h2v[10], ev[6], d1v[10], d2v[16];

    layer2<20, 8, true >(sw + OFF_W1, sw + OFF_B1, myrow, h1v);
    layer2<15, 5, true >(sw + OFF_W2, sw + OFF_B2, h1v,   h2v);
    layer2<10, 3, false>(sw + OFF_W3, sw + OFF_B3, h2v,   ev);

    if (n < N) {
#pragma unroll
        for (int i = 0; i < 5; i++) enc_out[(size_t)n * 5 + i] = ev[i];
    }

    layer2< 5, 5, true >(sw + OFF_W4, sw + OFF_B4, ev,  d1v);
    layer2<10, 8, true >(sw + OFF_W5, sw + OFF_B5, d1v, d2v);
    layer2<15, 10, false>(sw + OFF_W6, sw + OFF_B6, d2v, myrow);

    __syncthreads();

    // ---- export decoded tile (coalesced float4) ----
#pragma unroll
    for (int i = 0; i < 5; i++) {
        int  lf4 = tid + i * BLK;
        long f4  = f4base + lf4;
        if (f4 < f4total) {
            int rr = lf4 / 5, q = lf4 % 5;
            const float* s = se + rr * EMB_PAD + q * 4;
            reinterpret_cast<float4*>(dec_out)[f4] =
                make_float4(s[0], s[1], s[2], s[3]);
        }
    }
}

// ---------------------------------------------------------------------------
extern "C" void kernel_launch(void* const* d_in, const int* in_sizes, int n_in,
                              void* d_out, int out_size)
{
    const float* features = (const float*)d_in[0];
    const int*   adj      = (const int*)d_in[1];
    const float* We1 = (const float*)d_in[2];  const float* be1 = (const float*)d_in[3];
    const float* We2 = (const float*)d_in[4];  const float* be2 = (const float*)d_in[5];
    const float* We3 = (const float*)d_in[6];  const float* be3 = (const float*)d_in[7];
    const float* Wd1 = (const float*)d_in[8];  const float* bd1 = (const float*)d_in[9];
    const float* Wd2 = (const float*)d_in[10]; const float* bd2 = (const float*)d_in[11];
    const float* Wd3 = (const float*)d_in[12]; const float* bd3 = (const float*)d_in[13];

    int N = in_sizes[0] / NODELEN;

    float* out = (float*)d_out;
    float* enc_out = out;                     // [N,5]
    float* dec_out = out + (size_t)N * 5;     // [N,20]
    float* emb_out = out + (size_t)N * 25;    // [N,20]

    int pack_blocks = (N * PADH + 255) / 256;
    pack_features_kernel<<<pack_blocks, 256>>>(features, N);

    int hop_blocks = (N + 15) / 16;   // one warp per 2 nodes
    hop1_kernel<<<hop_blocks, 256>>>(adj, N);

    int fused_blocks = (N + BLK - 1) / BLK;
    hop2_mlp_kernel<<<fused_blocks, BLK>>>(features, adj,
                                           We1, be1, We2, be2, We3, be3,
                                           Wd1, bd1, Wd2, bd2, Wd3, bd3,
                                           emb_out, enc_out, dec_out, N);
}

// round 10
// speedup vs baseline: 1.0183x; 1.0183x over previous
#include <cuda_runtime.h>
#include <cuda_fp16.h>

#define NODELEN 10
#define DEG 32
#define MAXN 200000
#define PADH 16   // halves per row: 32B = one sector, sector-aligned

// Allocation-free scratch: fp16 gather tables, one sector per row.
__device__ __half g_featH[(size_t)MAXN * PADH];
__device__ __half g_h1H[(size_t)MAXN * PADH];

// ---------------------------------------------------------------------------
// Pack: features [N,10] fp32 -> g_featH [N,16] fp16 (zero padded).
// One thread per half2 slot: one aligned LDG.64 + one STG.32.
// ---------------------------------------------------------------------------
__global__ __launch_bounds__(256) void pack_features_kernel(
    const float* __restrict__ features, int N)
{
    int idx = blockIdx.x * blockDim.x + threadIdx.x;   // half2 slot
    if (idx >= N * (PADH / 2)) return;
    int n = idx >> 3;
    int p = idx & 7;
    __half2 h = __floats2half2_rn(0.f, 0.f);
    if (p < 5) {   // pairs 0..4 hold the 10 real features
        float2 v = *reinterpret_cast<const float2*>(
            features + (size_t)n * NODELEN + 2 * p);
        h = __floats2half2_rn(v.x, v.y);
    }
    reinterpret_cast<__half2*>(g_featH)[idx] = h;
}

// ---------------------------------------------------------------------------
// Hop 1: one warp per FOUR nodes (32 gather LDGs in flight). Each gathered
// row = 16 halves = 32B = one sector -> 1 L1tex wavefront per random row.
// Lane l: r = l>>3 (0..3), j = l&7 (dim pair). Node t gathered into a_t;
// after the xor(8,16) butterfly every lane holds the full 32-row sum of all
// four accumulators; lane group g writes node g's pair j.
// ---------------------------------------------------------------------------
__global__ __launch_bounds__(256) void hop1_kernel(
    const int* __restrict__ adj, int N)
{
    int w    = (blockIdx.x * blockDim.x + threadIdx.x) >> 5;
    int lane = threadIdx.x & 31;
    int n0 = 4 * w;
    if (n0 >= N) return;

    int nb0 = (n0     < N) ? adj[(size_t)(n0    ) * DEG + lane] : 0;
    int nb1 = (n0 + 1 < N) ? adj[(size_t)(n0 + 1) * DEG + lane] : 0;
    int nb2 = (n0 + 2 < N) ? adj[(size_t)(n0 + 2) * DEG + lane] : 0;
    int nb3 = (n0 + 3 < N) ? adj[(size_t)(n0 + 3) * DEG + lane] : 0;

    int r = lane >> 3, j = lane & 7;
    float2 a0 = make_float2(0.f, 0.f), a1 = a0, a2 = a0, a3 = a0;
#pragma unroll
    for (int i = 0; i < 8; i++) {
        int m0 = __shfl_sync(0xffffffffu, nb0, 4 * i + r);
        int m1 = __shfl_sync(0xffffffffu, nb1, 4 * i + r);
        int m2 = __shfl_sync(0xffffffffu, nb2, 4 * i + r);
        int m3 = __shfl_sync(0xffffffffu, nb3, 4 * i + r);
        float2 v0 = __half22float2(*reinterpret_cast<const __half2*>(
            g_featH + (size_t)m0 * PADH + 2 * j));
        float2 v1 = __half22float2(*reinterpret_cast<const __half2*>(
            g_featH + (size_t)m1 * PADH + 2 * j));
        float2 v2 = __half22float2(*reinterpret_cast<const __half2*>(
            g_featH + (size_t)m2 * PADH + 2 * j));
        float2 v3 = __half22float2(*reinterpret_cast<const __half2*>(
            g_featH + (size_t)m3 * PADH + 2 * j));
        a0.x += v0.x; a0.y += v0.y;
        a1.x += v1.x; a1.y += v1.y;
        a2.x += v2.x; a2.y += v2.y;
        a3.x += v3.x; a3.y += v3.y;
    }
#pragma unroll
    for (int off = 8; off < 32; off <<= 1) {
        a0.x += __shfl_xor_sync(0xffffffffu, a0.x, off);
        a0.y += __shfl_xor_sync(0xffffffffu, a0.y, off);
        a1.x += __shfl_xor_sync(0xffffffffu, a1.x, off);
        a1.y += __shfl_xor_sync(0xffffffffu, a1.y, off);
        a2.x += __shfl_xor_sync(0xffffffffu, a2.x, off);
        a2.y += __shfl_xor_sync(0xffffffffu, a2.y, off);
        a3.x += __shfl_xor_sync(0xffffffffu, a3.x, off);
        a3.y += __shfl_xor_sync(0xffffffffu, a3.y, off);
    }

    // lane group g = r writes node n0+g, pair j
    int node = n0 + r;
    if (node < N) {
        float2 s = (r == 0) ? a0 : (r == 1) ? a1 : (r == 2) ? a2 : a3;
        float vx = s.x * (1.f / 32.f);
        float vy = s.y * (1.f / 32.f);
        if (j == 0) vx = 0.f;                // h1[:,0] = 0
        *reinterpret_cast<__half2*>(g_h1H + (size_t)node * PADH + 2 * j) =
            __floats2half2_rn(vx, vy);
    }
}

// ---------------------------------------------------------------------------
// f32x2 helpers (sm_103a packed FFMA2)
// ---------------------------------------------------------------------------
typedef unsigned long long u64;

__device__ __forceinline__ u64 pk2(float lo, float hi) {
    u64 r; asm("mov.b64 %0,{%1,%2};" : "=l"(r) : "f"(lo), "f"(hi)); return r;
}
__device__ __forceinline__ void up2(u64 v, float& lo, float& hi) {
    asm("mov.b64 {%0,%1},%2;" : "=f"(lo), "=f"(hi) : "l"(v));
}
__device__ __forceinline__ u64 fma2(u64 a, u64 b, u64 c) {
    u64 d; asm("fma.rn.f32x2 %0,%1,%2,%3;" : "=l"(d) : "l"(a), "l"(b), "l"(c));
    return d;
}

template<int I, int P, bool RELU>
__device__ __forceinline__ void layer2(const u64* __restrict__ w,
                                       const u64* __restrict__ b,
                                       const float* __restrict__ in,
                                       float* __restrict__ out)
{
    u64 acc[P];
#pragma unroll
    for (int p = 0; p < P; p++) acc[p] = b[p];
#pragma unroll
    for (int j = 0; j < I; j++) {
        float xv = in[j];
        u64 xj = pk2(xv, xv);
#pragma unroll
        for (int p = 0; p < P; p++)
            acc[p] = fma2(w[j * P + p], xj, acc[p]);
    }
#pragma unroll
    for (int p = 0; p < P; p++) {
        float lo, hi; up2(acc[p], lo, hi);
        if (RELU) { lo = fmaxf(lo, 0.f); hi = fmaxf(hi, 0.f); }
        out[2 * p]     = lo;
        out[2 * p + 1] = hi;
    }
}

// smem u64 offsets for the 6 layers (W then biases)
#define OFF_W1 0      // 20*8  = 160
#define OFF_W2 160    // 15*5  = 75
#define OFF_W3 235    // 10*3  = 30
#define OFF_W4 265    // 5*5   = 25
#define OFF_W5 290    // 10*8  = 80
#define OFF_W6 370    // 15*10 = 150
#define OFF_B1 520
#define OFF_B2 528
#define OFF_B3 533
#define OFF_B4 536
#define OFF_B5 541
#define OFF_B6 549
#define SW_U64 560

#define BLK 256
#define EMB_PAD 21   // odd stride -> conflict-free LDS

// ---------------------------------------------------------------------------
// FUSED hop2 + emb + MLP. Block = 256 threads = 256 nodes.
// ---------------------------------------------------------------------------
__global__ __launch_bounds__(BLK) void hop2_mlp_kernel(
    const float* __restrict__ features, const int* __restrict__ adj,
    const float* __restrict__ We1, const float* __restrict__ be1,
    const float* __restrict__ We2, const float* __restrict__ be2,
    const float* __restrict__ We3, const float* __restrict__ be3,
    const float* __restrict__ Wd1, const float* __restrict__ bd1,
    const float* __restrict__ Wd2, const float* __restrict__ bd2,
    const float* __restrict__ Wd3, const float* __restrict__ bd3,
    float* __restrict__ emb_out, float* __restrict__ enc_out,
    float* __restrict__ dec_out, int N)
{
    __shared__ __align__(16) u64 sw[SW_U64];
    __shared__ float se[BLK * EMB_PAD];

    const int tid  = threadIdx.x;
    const int wid  = tid >> 5;
    const int lane = tid & 31;
    const int base = blockIdx.x * BLK;

    // ---- weight prep (all warps take a slice; barrier below covers it) ----
    {
        const float* Ws[6] = {We1, We2, We3, Wd1, Wd2, Wd3};
        const float* Bs[6] = {be1, be2, be3, bd1, bd2, bd3};
        const int Is[6] = {20, 15, 10, 5, 10, 15};
        const int Os[6] = {15, 10, 5, 10, 15, 20};
        const int Ps[6] = {8, 5, 3, 5, 8, 10};
        const int oW[6] = {OFF_W1, OFF_W2, OFF_W3, OFF_W4, OFF_W5, OFF_W6};
        const int oB[6] = {OFF_B1, OFF_B2, OFF_B3, OFF_B4, OFF_B5, OFF_B6};
        for (int l = 0; l < 6; l++) {
            int I = Is[l], O = Os[l], P = Ps[l];
            const float* W = Ws[l];
            for (int idx = tid; idx < I * P; idx += BLK) {
                int j = idx / P, p = idx % P;
                int r0 = 2 * p, r1 = 2 * p + 1;
                float w0 = (r0 < O) ? W[r0 * I + j] : 0.f;
                float w1 = (r1 < O) ? W[r1 * I + j] : 0.f;
                reinterpret_cast<float2*>(sw)[oW[l] + idx] = make_float2(w0, w1);
            }
            const float* B = Bs[l];
            for (int p = tid; p < P; p += BLK) {
                int r0 = 2 * p, r1 = 2 * p + 1;
                float b0 = (r0 < O) ? B[r0] : 0.f;
                float b1 = (r1 < O) ? B[r1] : 0.f;
                reinterpret_cast<float2*>(sw)[oB[l] + p] = make_float2(b0, b1);
            }
        }
    }

    // ---- Phase A: gather agg + self features into se tile ----
    const int r = lane >> 3, j = lane & 7;
#pragma unroll 2
    for (int it = 0; it < 16; it++) {
        int ln0 = (wid << 5) + 2 * it;
        int ln1 = ln0 + 1;
        int n0 = base + ln0, n1 = base + ln1;
        bool v0b = (n0 < N), v1b = (n1 < N);

        int nb0 = v0b ? adj[(size_t)n0 * DEG + lane] : 0;
        int nb1 = v1b ? adj[(size_t)n1 * DEG + lane] : 0;

        float2 a0 = make_float2(0.f, 0.f), a1 = make_float2(0.f, 0.f);
#pragma unroll
        for (int i = 0; i < 8; i++) {
            int m0 = __shfl_sync(0xffffffffu, nb0, 4 * i + r);
            int m1 = __shfl_sync(0xffffffffu, nb1, 4 * i + r);
            float2 q0 = __half22float2(*reinterpret_cast<const __half2*>(
                g_h1H + (size_t)m0 * PADH + 2 * j));
            float2 q1 = __half22float2(*reinterpret_cast<const __half2*>(
                g_h1H + (size_t)m1 * PADH + 2 * j));
            a0.x += q0.x; a0.y += q0.y;
            a1.x += q1.x; a1.y += q1.y;
        }
#pragma unroll
        for (int off = 8; off < 32; off <<= 1) {
            a0.x += __shfl_xor_sync(0xffffffffu, a0.x, off);
            a0.y += __shfl_xor_sync(0xffffffffu, a0.y, off);
            a1.x += __shfl_xor_sync(0xffffffffu, a1.x, off);
            a1.y += __shfl_xor_sync(0xffffffffu, a1.y, off);
        }

        // agg -> se cols 10..19 (pairs j=0..4), col 10 zeroed
        if (lane < 16 && j < 5) {
            int  ln    = (lane >> 3) ? ln1 : ln0;
            bool valid = (lane >> 3) ? v1b : v0b;
            float2 s   = (lane >> 3) ? a1 : a0;
            if (valid) {
                float vx = s.x * (1.f / 32.f);
                float vy = s.y * (1.f / 32.f);
                if (j == 0) vx = 0.f;        // emb[:,NODELEN] = 0
                se[ln * EMB_PAD + 10 + 2 * j]     = vx;
                se[ln * EMB_PAD + 10 + 2 * j + 1] = vy;
            }
        }
        // self features -> se cols 0..9, col 0 zeroed
        if (lane >= 12) {
            int d, ln, node; bool valid;
            if (lane < 22) { d = lane - 12; ln = ln0; node = n0; valid = v0b; }
            else           { d = lane - 22; ln = ln1; node = n1; valid = v1b; }
            if (valid) {
                float f = (d == 0) ? 0.f : features[(size_t)node * NODELEN + d];
                se[ln * EMB_PAD + d] = f;
            }
        }
    }
    __syncthreads();

    // ---- export emb tile (coalesced float4) ----
    const long f4base  = (long)base * 5;
    const long f4total = (long)N * 5;
#pragma unroll
    for (int i = 0; i < 5; i++) {
        int  lf4 = tid + i * BLK;
        long f4  = f4base + lf4;
        if (f4 < f4total) {
            int rr = lf4 / 5, q = lf4 % 5;
            const float* s = se + rr * EMB_PAD + q * 4;
            reinterpret_cast<float4*>(emb_out)[f4] =
                make_float4(s[0], s[1], s[2], s[3]);
        }
    }
    __syncthreads();   // emb export must finish before decode overwrites se

    // ---- Phase B: MLP, one node per thread ----
    const int n = base + tid;
    float* myrow = se + tid * EMB_PAD;

    float h1v[16], h2v[10], ev[6], d1v[10], d2v[16];

    layer2<20, 8, true >(sw + OFF_W1, sw + OFF_B1, myrow, h1v);
    layer2<15, 5, true >(sw + OFF_W2, sw + OFF_B2, h1v,   h2v);
    layer2<10, 3, false>(sw + OFF_W3, sw + OFF_B3, h2v,   ev);

    if (n < N) {
#pragma unroll
        for (int i = 0; i < 5; i++) enc_out[(size_t)n * 5 + i] = ev[i];
    }

    layer2< 5, 5, true >(sw + OFF_W4, sw + OFF_B4, ev,  d1v);
    layer2<10, 8, true >(sw + OFF_W5, sw + OFF_B5, d1v, d2v);
    layer2<15, 10, false>(sw + OFF_W6, sw + OFF_B6, d2v, myrow);

    __syncthreads();

    // ---- export decoded tile (coalesced float4) ----
#pragma unroll
    for (int i = 0; i < 5; i++) {
        int  lf4 = tid + i * BLK;
        long f4  = f4base + lf4;
        if (f4 < f4total) {
            int rr = lf4 / 5, q = lf4 % 5;
            const float* s = se + rr * EMB_PAD + q * 4;
            reinterpret_cast<float4*>(dec_out)[f4] =
                make_float4(s[0], s[1], s[2], s[3]);
        }
    }
}

// ---------------------------------------------------------------------------
extern "C" void kernel_launch(void* const* d_in, const int* in_sizes, int n_in,
                              void* d_out, int out_size)
{
    const float* features = (const float*)d_in[0];
    const int*   adj      = (const int*)d_in[1];
    const float* We1 = (const float*)d_in[2];  const float* be1 = (const float*)d_in[3];
    const float* We2 = (const float*)d_in[4];  const float* be2 = (const float*)d_in[5];
    const float* We3 = (const float*)d_in[6];  const float* be3 = (const float*)d_in[7];
    const float* Wd1 = (const float*)d_in[8];  const float* bd1 = (const float*)d_in[9];
    const float* Wd2 = (const float*)d_in[10]; const float* bd2 = (const float*)d_in[11];
    const float* Wd3 = (const float*)d_in[12]; const float* bd3 = (const float*)d_in[13];

    int N = in_sizes[0] / NODELEN;

    float* out = (float*)d_out;
    float* enc_out = out;                     // [N,5]
    float* dec_out = out + (size_t)N * 5;     // [N,20]
    float* emb_out = out + (size_t)N * 25;    // [N,20]

    int pack_blocks = (N * (PADH / 2) + 255) / 256;
    pack_features_kernel<<<pack_blocks, 256>>>(features, N);

    int hop1_blocks = (N + 31) / 32;   // one warp per 4 nodes, 8 warps/block
    hop1_kernel<<<hop1_blocks, 256>>>(adj, N);

    int fused_blocks = (N + BLK - 1) / BLK;
    hop2_mlp_kernel<<<fused_blocks, BLK>>>(features, adj,
                                           We1, be1, We2, be2, We3, be3,
                                           Wd1, bd1, Wd2, bd2, Wd3, bd3,
                                           emb_out, enc_out, dec_out, N);
}